// round 14
// baseline (speedup 1.0000x reference)
#include <cuda_runtime.h>
#include <cuda_bf16.h>
#include <math.h>
#include <stdint.h>

// Problem constants
#define BB 2
#define SS 2048
#define DD 1024
#define NH 16
#define DKH 64
#define MROWS (BB * SS)   // 4096

// ---------------- scratch (device globals; no allocation allowed) ----------------
__device__ float g_Q[MROWS * DD];
__device__ float g_K[MROWS * DD];
__device__ float g_V[MROWS * DD];
__device__ float g_X[MROWS * DD];
__device__ float g_qc[MROWS * DD];
__device__ float g_kc[MROWS * DD];
__device__ float g_vc[MROWS * DD];
__device__ float g_wc[4][DD * DD];

__device__ __forceinline__ uint32_t f2tf32(float x) {
    uint32_t r;
    asm("cvt.rna.tf32.f32 %0, %1;" : "=r"(r) : "f"(x));
    return r;
}
__device__ __forceinline__ float f2tf32f(float x) {
    return __uint_as_float(f2tf32(x));
}

__device__ __forceinline__ void cp_async16(uint32_t dst, const void* src) {
    asm volatile("cp.async.cg.shared.global [%0], [%1], 16;" :: "r"(dst), "l"(src));
}
#define CP_COMMIT()  asm volatile("cp.async.commit_group;" ::: "memory")
#define CP_WAIT1()   asm volatile("cp.async.wait_group 1;" ::: "memory")

// ---------------- fused tf32 conversion prep (all 7 tensors, one launch) ----------------
#define NI4 (MROWS * DD / 4)   // 2^20
#define NW4 (DD * DD / 4)      // 2^18
#define PREP_TOTAL (3 * NI4 + 4 * NW4)

__global__ __launch_bounds__(256) void prep_all(
    const float* __restrict__ q, const float* __restrict__ k, const float* __restrict__ v,
    const float* __restrict__ wq, const float* __restrict__ wk,
    const float* __restrict__ wv, const float* __restrict__ wo,
    float* __restrict__ qc, float* __restrict__ kc, float* __restrict__ vc,
    float* __restrict__ wqc, float* __restrict__ wkc,
    float* __restrict__ wvc, float* __restrict__ woc)
{
    long i = (long)blockIdx.x * 256 + threadIdx.x;
    const float4* s;
    float4* d;
    long off;
    if (i < 3L * NI4) {
        int r = (int)(i >> 20);
        off = i & (NI4 - 1);
        s = (const float4*)(r == 0 ? q : (r == 1 ? k : v));
        d = (float4*)(r == 0 ? qc : (r == 1 ? kc : vc));
    } else {
        long j = i - 3L * NI4;
        int r = (int)(j >> 18);
        off = j & (NW4 - 1);
        s = (const float4*)(r == 0 ? wq : (r == 1 ? wk : (r == 2 ? wv : wo)));
        d = (float4*)(r == 0 ? wqc : (r == 1 ? wkc : (r == 2 ? wvc : woc)));
    }
    float4 t = s[off];
    t.x = f2tf32f(t.x); t.y = f2tf32f(t.y);
    t.z = f2tf32f(t.z); t.w = f2tf32f(t.w);
    d[off] = t;
}

// ---------------- TF32 GEMM, cp.async 3-stage, 4 warps, 64x64 warp tiles ----------------
#define GST 3
#define GSTAGE_FLOATS 8192
#define GEMM_SMEM (GST * GSTAGE_FLOATS * 4)   // 98304 B

__device__ __forceinline__ void gemm_stage_copy(
    const float* __restrict__ A, const float* __restrict__ W,
    int m0, int n0, int k0, uint32_t sA, uint32_t sB, int tid)
{
    #pragma unroll
    for (int u = 0; u < 8; u++) {
        int idx = tid + u * 128;
        int row = idx >> 3;
        int c   = idx & 7;
        int swz = c ^ (row & 7);
        cp_async16(sA + (uint32_t)(row * 128 + swz * 16),
                   A + (size_t)(m0 + row) * DD + k0 + c * 4);
        cp_async16(sB + (uint32_t)(row * 128 + swz * 16),
                   W + (size_t)(n0 + row) * DD + k0 + c * 4);
    }
}

__device__ __forceinline__ void gemm_body(
    const float* __restrict__ A, const float* __restrict__ W,
    const float* __restrict__ bias, float* __restrict__ C, int round_out)
{
    extern __shared__ float sm[];
    const uint32_t sbase = (uint32_t)__cvta_generic_to_shared(sm);

    const int tid  = threadIdx.x;
    const int lane = tid & 31;
    const int warp = tid >> 5;
    const int wm = (warp & 1) * 64;
    const int wn = (warp >> 1) * 64;
    const int m0 = blockIdx.y * 128;
    const int n0 = blockIdx.x * 128;
    const int lr = lane >> 2;
    const int lc = lane & 3;

    float acc[4][8][4];
    #pragma unroll
    for (int i = 0; i < 4; i++)
        #pragma unroll
        for (int j = 0; j < 8; j++)
            #pragma unroll
            for (int t = 0; t < 4; t++) acc[i][j][t] = 0.f;

    const int NIT = DD / 32;

    gemm_stage_copy(A, W, m0, n0, 0, sbase, sbase + 4096 * 4, tid);
    CP_COMMIT();
    gemm_stage_copy(A, W, m0, n0, 32,
                    sbase + GSTAGE_FLOATS * 4, sbase + (GSTAGE_FLOATS + 4096) * 4, tid);
    CP_COMMIT();

    for (int it = 0; it < NIT; it++) {
        CP_WAIT1();
        __syncthreads();

        if (it + 2 < NIT) {
            int slot = (it + 2) % GST;
            gemm_stage_copy(A, W, m0, n0, (it + 2) * 32,
                            sbase + (uint32_t)(slot * GSTAGE_FLOATS) * 4,
                            sbase + (uint32_t)(slot * GSTAGE_FLOATS + 4096) * 4, tid);
        }
        CP_COMMIT();

        const float* As = sm + (it % GST) * GSTAGE_FLOATS;
        const float* Bs = As + 4096;

        #pragma unroll
        for (int ks = 0; ks < 4; ks++) {
            const int sw0 = (((2 * ks)     ^ lr) << 2) + lc;
            const int sw1 = (((2 * ks + 1) ^ lr) << 2) + lc;
            uint32_t a[4][4], b[8][2];
            #pragma unroll
            for (int mt = 0; mt < 4; mt++) {
                int r = wm + mt * 16 + lr;
                a[mt][0] = __float_as_uint(As[r * 32 + sw0]);
                a[mt][1] = __float_as_uint(As[(r + 8) * 32 + sw0]);
                a[mt][2] = __float_as_uint(As[r * 32 + sw1]);
                a[mt][3] = __float_as_uint(As[(r + 8) * 32 + sw1]);
            }
            #pragma unroll
            for (int nt = 0; nt < 8; nt++) {
                int cn = wn + nt * 8 + lr;
                b[nt][0] = __float_as_uint(Bs[cn * 32 + sw0]);
                b[nt][1] = __float_as_uint(Bs[cn * 32 + sw1]);
            }
            #pragma unroll
            for (int mt = 0; mt < 4; mt++)
                #pragma unroll
                for (int nt = 0; nt < 8; nt++)
                    asm volatile(
                        "mma.sync.aligned.m16n8k8.row.col.f32.tf32.tf32.f32 "
                        "{%0,%1,%2,%3}, {%4,%5,%6,%7}, {%8,%9}, {%0,%1,%2,%3};"
                        : "+f"(acc[mt][nt][0]), "+f"(acc[mt][nt][1]),
                          "+f"(acc[mt][nt][2]), "+f"(acc[mt][nt][3])
                        : "r"(a[mt][0]), "r"(a[mt][1]), "r"(a[mt][2]), "r"(a[mt][3]),
                          "r"(b[nt][0]), "r"(b[nt][1]));
        }
    }

    #pragma unroll
    for (int nt = 0; nt < 8; nt++) {
        int col = n0 + wn + nt * 8 + lc * 2;
        float b0 = bias[col], b1 = bias[col + 1];
        #pragma unroll
        for (int mt = 0; mt < 4; mt++) {
            int r0 = m0 + wm + mt * 16 + lr;
            float2 o0, o1;
            if (round_out) {
                o0 = make_float2(f2tf32f(acc[mt][nt][0] + b0), f2tf32f(acc[mt][nt][1] + b1));
                o1 = make_float2(f2tf32f(acc[mt][nt][2] + b0), f2tf32f(acc[mt][nt][3] + b1));
            } else {
                o0 = make_float2(acc[mt][nt][0] + b0, acc[mt][nt][1] + b1);
                o1 = make_float2(acc[mt][nt][2] + b0, acc[mt][nt][3] + b1);
            }
            *(float2*)&C[(size_t)r0 * DD + col] = o0;
            *(float2*)&C[(size_t)(r0 + 8) * DD + col] = o1;
        }
    }
}

__global__ __launch_bounds__(128, 2) void gemm_qkv_fused(
    const float* __restrict__ A0, const float* __restrict__ A1, const float* __restrict__ A2,
    const float* __restrict__ W0, const float* __restrict__ W1, const float* __restrict__ W2,
    const float* __restrict__ b0, const float* __restrict__ b1, const float* __restrict__ b2,
    float* __restrict__ C0, float* __restrict__ C1, float* __restrict__ C2)
{
    int z = blockIdx.z;
    const float* A = (z == 0) ? A0 : (z == 1) ? A1 : A2;
    const float* W = (z == 0) ? W0 : (z == 1) ? W1 : W2;
    const float* bi = (z == 0) ? b0 : (z == 1) ? b1 : b2;
    float* C = (z == 0) ? C0 : (z == 1) ? C1 : C2;
    gemm_body(A, W, bi, C, 1);
}

__global__ __launch_bounds__(128, 2) void gemm_out_kernel(
    const float* __restrict__ A, const float* __restrict__ W,
    const float* __restrict__ bias, float* __restrict__ C)
{
    gemm_body(A, W, bias, C, 0);
}

// ---------------- Flash attention (causal), TF32 mma ----------------
// Q-tile 128 rows, 256 threads (8 warps x 16 q-rows); K/V 64-row tiles,
// cp.async double-buffered. Each K/V tile now serves 128 q-rows.
#define FQT 128
#define FKT 64
#define FSTRK 68
#define FSTRV 72
#define FSTAGE (FKT * FSTRK + FKT * FSTRV)        // 8960 floats per stage
#define FLASH_SMEM (2 * FSTAGE * 4)               // 71680 bytes

__device__ __forceinline__ void flash_copy(
    const float* __restrict__ K, const float* __restrict__ V,
    size_t gbase, uint32_t sK, uint32_t sV, int tid)
{
    #pragma unroll
    for (int u = 0; u < 4; u++) {
        int idx = tid + u * 256;          // 0..1023
        int row = idx >> 4;               // 0..63
        int c   = idx & 15;               // 16B chunk
        cp_async16(sK + (uint32_t)(row * (FSTRK * 4) + c * 16),
                   K + gbase + (size_t)row * DD + c * 4);
        cp_async16(sV + (uint32_t)(row * (FSTRV * 4) + c * 16),
                   V + gbase + (size_t)row * DD + c * 4);
    }
}

__global__ __launch_bounds__(256, 2) void flash_mma_kernel(
    const float* __restrict__ Q, const float* __restrict__ K,
    const float* __restrict__ V, float* __restrict__ O)
{
    extern __shared__ float smem[];
    const uint32_t sbase = (uint32_t)__cvta_generic_to_shared(smem);

    const int tid  = threadIdx.x;
    const int lane = tid & 31;
    const int warp = tid >> 5;            // 0..7
    const int lr = lane >> 2;
    const int lc = lane & 3;
    const int qt = gridDim.x - 1 - blockIdx.x;   // heavy tiles first
    const int h  = blockIdx.y;
    const int b  = blockIdx.z;
    const int q0 = qt * FQT;
    const int lw = warp * 16 + lr;        // local q row (0..127)
    const float scale = 0.125f;

    const int srcA = (lane & ~3) + (lc >> 1);
    const int srcB = srcA + 2;
    const bool hi  = (lc & 1);

    const size_t hbase = ((size_t)(b * SS)) * DD + h * DKH;

    // issue tile-0 copy immediately
    flash_copy(K, V, hbase, sbase, sbase + FKT * FSTRK * 4, tid);
    CP_COMMIT();

    // ---- Q fragments to registers (x0.125, exact on tf32 values) ----
    uint32_t qa[8][4];
    {
        const float* qr0 = Q + hbase + (size_t)(q0 + warp*16 + lr) * DD;
        const float* qr1 = qr0 + 8 * DD;
        #pragma unroll
        for (int ks = 0; ks < 8; ks++) {
            const int kb = ks * 8;
            qa[ks][0] = __float_as_uint(qr0[kb + lc] * scale);
            qa[ks][1] = __float_as_uint(qr1[kb + lc] * scale);
            qa[ks][2] = __float_as_uint(qr0[kb + 4 + lc] * scale);
            qa[ks][3] = __float_as_uint(qr1[kb + 4 + lc] * scale);
        }
    }

    float m0v = -1e30f, m1v = -1e30f, l0 = 0.f, l1 = 0.f;
    float o_acc[8][4];
    #pragma unroll
    for (int nt = 0; nt < 8; nt++)
        #pragma unroll
        for (int t = 0; t < 4; t++) o_acc[nt][t] = 0.f;

    const int ntiles = 2 * qt + 2;        // causal: k up to q0+127
    const int tdiag  = 2 * qt;            // first tile needing the mask

    for (int t = 0; t < ntiles; t++) {
        // issue next tile's copy into the other buffer
        if (t + 1 < ntiles) {
            uint32_t nb = sbase + ((t + 1) & 1) * (FSTAGE * 4);
            flash_copy(K, V, hbase + (size_t)(t + 1) * FKT * DD,
                       nb, nb + FKT * FSTRK * 4, tid);
        }
        CP_COMMIT();
        CP_WAIT1();
        __syncthreads();

        const float* Ks = smem + (t & 1) * FSTAGE;
        const float* Vs = Ks + FKT * FSTRK;

        // ---- S = Q @ K^T ----
        float s[8][4];
        #pragma unroll
        for (int nt = 0; nt < 8; nt++)
            #pragma unroll
            for (int x = 0; x < 4; x++) s[nt][x] = 0.f;

        #pragma unroll
        for (int ks = 0; ks < 8; ks++) {
            const int kb = ks * 8;
            #pragma unroll
            for (int nt = 0; nt < 8; nt++) {
                uint32_t b0 = __float_as_uint(Ks[(nt*8 + lr) * FSTRK + kb + lc]);
                uint32_t b1 = __float_as_uint(Ks[(nt*8 + lr) * FSTRK + kb + 4 + lc]);
                asm volatile(
                    "mma.sync.aligned.m16n8k8.row.col.f32.tf32.tf32.f32 "
                    "{%0,%1,%2,%3}, {%4,%5,%6,%7}, {%8,%9}, {%0,%1,%2,%3};"
                    : "+f"(s[nt][0]), "+f"(s[nt][1]), "+f"(s[nt][2]), "+f"(s[nt][3])
                    : "r"(qa[ks][0]), "r"(qa[ks][1]), "r"(qa[ks][2]), "r"(qa[ks][3]),
                      "r"(b0), "r"(b1));
            }
        }

        // ---- causal mask on the two diagonal tiles ----
        if (t >= tdiag) {
            const int jbase = (t - tdiag) * FKT;   // local k offset within 128-row q tile
            #pragma unroll
            for (int nt = 0; nt < 8; nt++) {
                int c0 = jbase + nt * 8 + lc * 2;
                if (c0     > lw)     s[nt][0] = -1e30f;
                if (c0 + 1 > lw)     s[nt][1] = -1e30f;
                if (c0     > lw + 8) s[nt][2] = -1e30f;
                if (c0 + 1 > lw + 8) s[nt][3] = -1e30f;
            }
        }

        // ---- online softmax ----
        float tm0 = -1e30f, tm1 = -1e30f;
        #pragma unroll
        for (int nt = 0; nt < 8; nt++) {
            tm0 = fmaxf(tm0, fmaxf(s[nt][0], s[nt][1]));
            tm1 = fmaxf(tm1, fmaxf(s[nt][2], s[nt][3]));
        }
        tm0 = fmaxf(tm0, __shfl_xor_sync(0xffffffffu, tm0, 1));
        tm0 = fmaxf(tm0, __shfl_xor_sync(0xffffffffu, tm0, 2));
        tm1 = fmaxf(tm1, __shfl_xor_sync(0xffffffffu, tm1, 1));
        tm1 = fmaxf(tm1, __shfl_xor_sync(0xffffffffu, tm1, 2));

        const float mn0 = fmaxf(m0v, tm0);
        const float mn1 = fmaxf(m1v, tm1);
        const float cr0 = __expf(m0v - mn0);
        const float cr1 = __expf(m1v - mn1);
        l0 *= cr0; l1 *= cr1;
        #pragma unroll
        for (int nt = 0; nt < 8; nt++) {
            o_acc[nt][0] *= cr0; o_acc[nt][1] *= cr0;
            o_acc[nt][2] *= cr1; o_acc[nt][3] *= cr1;
        }
        m0v = mn0; m1v = mn1;

        // ---- P = exp(S - m), rounded tf32, in registers ----
        #pragma unroll
        for (int nt = 0; nt < 8; nt++) {
            float p0 = __expf(s[nt][0] - mn0);
            float p1 = __expf(s[nt][1] - mn0);
            float p2 = __expf(s[nt][2] - mn1);
            float p3 = __expf(s[nt][3] - mn1);
            l0 += p0 + p1;
            l1 += p2 + p3;
            s[nt][0] = f2tf32f(p0); s[nt][1] = f2tf32f(p1);
            s[nt][2] = f2tf32f(p2); s[nt][3] = f2tf32f(p3);
        }

        // ---- O += P @ V ; a-frags via quad shuffles ----
        #pragma unroll
        for (int ks = 0; ks < 8; ks++) {
            const int kb = ks * 8;
            float t0 = __shfl_sync(0xffffffffu, s[ks][0], srcA);
            float t1 = __shfl_sync(0xffffffffu, s[ks][1], srcA);
            float t2 = __shfl_sync(0xffffffffu, s[ks][2], srcA);
            float t3 = __shfl_sync(0xffffffffu, s[ks][3], srcA);
            float v0 = __shfl_sync(0xffffffffu, s[ks][0], srcB);
            float v1 = __shfl_sync(0xffffffffu, s[ks][1], srcB);
            float v2 = __shfl_sync(0xffffffffu, s[ks][2], srcB);
            float v3 = __shfl_sync(0xffffffffu, s[ks][3], srcB);
            uint32_t a0 = __float_as_uint(hi ? t1 : t0);
            uint32_t a1 = __float_as_uint(hi ? t3 : t2);
            uint32_t a2 = __float_as_uint(hi ? v1 : v0);
            uint32_t a3 = __float_as_uint(hi ? v3 : v2);
            #pragma unroll
            for (int nt = 0; nt < 8; nt++) {
                uint32_t b0 = __float_as_uint(Vs[(kb + lc)     * FSTRV + nt*8 + lr]);
                uint32_t b1 = __float_as_uint(Vs[(kb + 4 + lc) * FSTRV + nt*8 + lr]);
                asm volatile(
                    "mma.sync.aligned.m16n8k8.row.col.f32.tf32.tf32.f32 "
                    "{%0,%1,%2,%3}, {%4,%5,%6,%7}, {%8,%9}, {%0,%1,%2,%3};"
                    : "+f"(o_acc[nt][0]), "+f"(o_acc[nt][1]),
                      "+f"(o_acc[nt][2]), "+f"(o_acc[nt][3])
                    : "r"(a0), "r"(a1), "r"(a2), "r"(a3), "r"(b0), "r"(b1));
            }
        }
        __syncthreads();   // all warps done with buf[t&1] before it is overwritten
    }

    // ---- finalize (tf32-rounded X for the output GEMM) ----
    l0 += __shfl_xor_sync(0xffffffffu, l0, 1);
    l0 += __shfl_xor_sync(0xffffffffu, l0, 2);
    l1 += __shfl_xor_sync(0xffffffffu, l1, 1);
    l1 += __shfl_xor_sync(0xffffffffu, l1, 2);
    const float inv0 = 1.0f / l0;
    const float inv1 = 1.0f / l1;

    const size_t obase = hbase + (size_t)q0 * DD;
    #pragma unroll
    for (int nt = 0; nt < 8; nt++) {
        int col = nt * 8 + lc * 2;
        *(float2*)(O + obase + (size_t)(warp*16 + lr) * DD + col) =
            make_float2(f2tf32f(o_acc[nt][0] * inv0), f2tf32f(o_acc[nt][1] * inv0));
        *(float2*)(O + obase + (size_t)(warp*16 + lr + 8) * DD + col) =
            make_float2(f2tf32f(o_acc[nt][2] * inv1), f2tf32f(o_acc[nt][3] * inv1));
    }
}

// ---------------- launch ----------------
extern "C" void kernel_launch(void* const* d_in, const int* in_sizes, int n_in,
                              void* d_out, int out_size)
{
    const float* q  = (const float*)d_in[0];
    const float* k  = (const float*)d_in[1];
    const float* v  = (const float*)d_in[2];
    // d_in[3] = mask (compile-time causal — unused)
    const float* wq = (const float*)d_in[4];
    const float* bq = (const float*)d_in[5];
    const float* wk = (const float*)d_in[6];
    const float* bk = (const float*)d_in[7];
    const float* wv = (const float*)d_in[8];
    const float* bv = (const float*)d_in[9];
    const float* wo = (const float*)d_in[10];
    const float* bo = (const float*)d_in[11];
    float* out = (float*)d_out;

    void *pQ, *pK, *pV, *pX, *pqc, *pkc, *pvc, *pwc;
    cudaGetSymbolAddress(&pQ, g_Q);
    cudaGetSymbolAddress(&pK, g_K);
    cudaGetSymbolAddress(&pV, g_V);
    cudaGetSymbolAddress(&pX, g_X);
    cudaGetSymbolAddress(&pqc, g_qc);
    cudaGetSymbolAddress(&pkc, g_kc);
    cudaGetSymbolAddress(&pvc, g_vc);
    cudaGetSymbolAddress(&pwc, g_wc);
    float* gQ = (float*)pQ;   float* gK = (float*)pK;
    float* gV = (float*)pV;   float* gX = (float*)pX;
    float* qc = (float*)pqc;  float* kc = (float*)pkc;
    float* vc = (float*)pvc;
    float* wqc = (float*)pwc;
    float* wkc = wqc + DD * DD;
    float* wvc = wqc + 2 * DD * DD;
    float* woc = wqc + 3 * DD * DD;

    cudaFuncSetAttribute(flash_mma_kernel,
                         cudaFuncAttributeMaxDynamicSharedMemorySize, FLASH_SMEM);
    cudaFuncSetAttribute(gemm_qkv_fused,
                         cudaFuncAttributeMaxDynamicSharedMemorySize, GEMM_SMEM);
    cudaFuncSetAttribute(gemm_out_kernel,
                         cudaFuncAttributeMaxDynamicSharedMemorySize, GEMM_SMEM);

    prep_all<<<PREP_TOTAL / 256, 256>>>(q, k, v, wq, wk, wv, wo,
                                        qc, kc, vc, wqc, wkc, wvc, woc);

    dim3 ggrid(DD / 128, MROWS / 128, 3);   // (8, 32, 3)
    gemm_qkv_fused<<<ggrid, 128, GEMM_SMEM>>>(qc, kc, vc, wqc, wkc, wvc,
                                              bq, bk, bv, gQ, gK, gV);

    dim3 fgrid(SS / FQT, NH, BB);           // (16, 16, 2)
    flash_mma_kernel<<<fgrid, 256, FLASH_SMEM>>>(gQ, gK, gV, gX);

    dim3 ogrid(DD / 128, MROWS / 128);
    gemm_out_kernel<<<ogrid, 128, GEMM_SMEM>>>(gX, woc, bo, out);
}

// round 15
// speedup vs baseline: 1.6513x; 1.6513x over previous
#include <cuda_runtime.h>
#include <cuda_bf16.h>
#include <math.h>
#include <stdint.h>

// Problem constants
#define BB 2
#define SS 2048
#define DD 1024
#define NH 16
#define DKH 64
#define MROWS (BB * SS)   // 4096

// ---------------- scratch (device globals; no allocation allowed) ----------------
__device__ float g_Q[MROWS * DD];
__device__ float g_K[MROWS * DD];
__device__ float g_V[MROWS * DD];
__device__ float g_X[MROWS * DD];
__device__ float g_qc[MROWS * DD];
__device__ float g_kc[MROWS * DD];
__device__ float g_vc[MROWS * DD];
__device__ float g_wc[4][DD * DD];

__device__ __forceinline__ uint32_t f2tf32(float x) {
    uint32_t r;
    asm("cvt.rna.tf32.f32 %0, %1;" : "=r"(r) : "f"(x));
    return r;
}
__device__ __forceinline__ float f2tf32f(float x) {
    return __uint_as_float(f2tf32(x));
}
__device__ __forceinline__ float ex2f(float x) {
    float r;
    asm("ex2.approx.f32 %0, %1;" : "=f"(r) : "f"(x));
    return r;
}

__device__ __forceinline__ void cp_async16(uint32_t dst, const void* src) {
    asm volatile("cp.async.cg.shared.global [%0], [%1], 16;" :: "r"(dst), "l"(src));
}
#define CP_COMMIT()  asm volatile("cp.async.commit_group;" ::: "memory")
#define CP_WAIT1()   asm volatile("cp.async.wait_group 1;" ::: "memory")

// ---------------- fused tf32 conversion prep (all 7 tensors, one launch) ----------------
#define NI4 (MROWS * DD / 4)   // 2^20
#define NW4 (DD * DD / 4)      // 2^18
#define PREP_TOTAL (3 * NI4 + 4 * NW4)

__global__ __launch_bounds__(256) void prep_all(
    const float* __restrict__ q, const float* __restrict__ k, const float* __restrict__ v,
    const float* __restrict__ wq, const float* __restrict__ wk,
    const float* __restrict__ wv, const float* __restrict__ wo,
    float* __restrict__ qc, float* __restrict__ kc, float* __restrict__ vc,
    float* __restrict__ wqc, float* __restrict__ wkc,
    float* __restrict__ wvc, float* __restrict__ woc)
{
    long i = (long)blockIdx.x * 256 + threadIdx.x;
    const float4* s;
    float4* d;
    long off;
    if (i < 3L * NI4) {
        int r = (int)(i >> 20);
        off = i & (NI4 - 1);
        s = (const float4*)(r == 0 ? q : (r == 1 ? k : v));
        d = (float4*)(r == 0 ? qc : (r == 1 ? kc : vc));
    } else {
        long j = i - 3L * NI4;
        int r = (int)(j >> 18);
        off = j & (NW4 - 1);
        s = (const float4*)(r == 0 ? wq : (r == 1 ? wk : (r == 2 ? wv : wo)));
        d = (float4*)(r == 0 ? wqc : (r == 1 ? wkc : (r == 2 ? wvc : woc)));
    }
    float4 t = s[off];
    t.x = f2tf32f(t.x); t.y = f2tf32f(t.y);
    t.z = f2tf32f(t.z); t.w = f2tf32f(t.w);
    d[off] = t;
}

// ---------------- TF32 GEMM, cp.async 3-stage, 4 warps, 64x64 warp tiles ----------------
#define GST 3
#define GSTAGE_FLOATS 8192
#define GEMM_SMEM (GST * GSTAGE_FLOATS * 4)   // 98304 B

__device__ __forceinline__ void gemm_stage_copy(
    const float* __restrict__ A, const float* __restrict__ W,
    int m0, int n0, int k0, uint32_t sA, uint32_t sB, int tid)
{
    #pragma unroll
    for (int u = 0; u < 8; u++) {
        int idx = tid + u * 128;
        int row = idx >> 3;
        int c   = idx & 7;
        int swz = c ^ (row & 7);
        cp_async16(sA + (uint32_t)(row * 128 + swz * 16),
                   A + (size_t)(m0 + row) * DD + k0 + c * 4);
        cp_async16(sB + (uint32_t)(row * 128 + swz * 16),
                   W + (size_t)(n0 + row) * DD + k0 + c * 4);
    }
}

__device__ __forceinline__ void gemm_body(
    const float* __restrict__ A, const float* __restrict__ W,
    const float* __restrict__ bias, float* __restrict__ C, int round_out)
{
    extern __shared__ float sm[];
    const uint32_t sbase = (uint32_t)__cvta_generic_to_shared(sm);

    const int tid  = threadIdx.x;
    const int lane = tid & 31;
    const int warp = tid >> 5;
    const int wm = (warp & 1) * 64;
    const int wn = (warp >> 1) * 64;
    const int m0 = blockIdx.y * 128;
    const int n0 = blockIdx.x * 128;
    const int lr = lane >> 2;
    const int lc = lane & 3;

    float acc[4][8][4];
    #pragma unroll
    for (int i = 0; i < 4; i++)
        #pragma unroll
        for (int j = 0; j < 8; j++)
            #pragma unroll
            for (int t = 0; t < 4; t++) acc[i][j][t] = 0.f;

    const int NIT = DD / 32;

    gemm_stage_copy(A, W, m0, n0, 0, sbase, sbase + 4096 * 4, tid);
    CP_COMMIT();
    gemm_stage_copy(A, W, m0, n0, 32,
                    sbase + GSTAGE_FLOATS * 4, sbase + (GSTAGE_FLOATS + 4096) * 4, tid);
    CP_COMMIT();

    for (int it = 0; it < NIT; it++) {
        CP_WAIT1();
        __syncthreads();

        if (it + 2 < NIT) {
            int slot = (it + 2) % GST;
            gemm_stage_copy(A, W, m0, n0, (it + 2) * 32,
                            sbase + (uint32_t)(slot * GSTAGE_FLOATS) * 4,
                            sbase + (uint32_t)(slot * GSTAGE_FLOATS + 4096) * 4, tid);
        }
        CP_COMMIT();

        const float* As = sm + (it % GST) * GSTAGE_FLOATS;
        const float* Bs = As + 4096;

        #pragma unroll
        for (int ks = 0; ks < 4; ks++) {
            const int sw0 = (((2 * ks)     ^ lr) << 2) + lc;
            const int sw1 = (((2 * ks + 1) ^ lr) << 2) + lc;
            uint32_t a[4][4], b[8][2];
            #pragma unroll
            for (int mt = 0; mt < 4; mt++) {
                int r = wm + mt * 16 + lr;
                a[mt][0] = __float_as_uint(As[r * 32 + sw0]);
                a[mt][1] = __float_as_uint(As[(r + 8) * 32 + sw0]);
                a[mt][2] = __float_as_uint(As[r * 32 + sw1]);
                a[mt][3] = __float_as_uint(As[(r + 8) * 32 + sw1]);
            }
            #pragma unroll
            for (int nt = 0; nt < 8; nt++) {
                int cn = wn + nt * 8 + lr;
                b[nt][0] = __float_as_uint(Bs[cn * 32 + sw0]);
                b[nt][1] = __float_as_uint(Bs[cn * 32 + sw1]);
            }
            #pragma unroll
            for (int mt = 0; mt < 4; mt++)
                #pragma unroll
                for (int nt = 0; nt < 8; nt++)
                    asm volatile(
                        "mma.sync.aligned.m16n8k8.row.col.f32.tf32.tf32.f32 "
                        "{%0,%1,%2,%3}, {%4,%5,%6,%7}, {%8,%9}, {%0,%1,%2,%3};"
                        : "+f"(acc[mt][nt][0]), "+f"(acc[mt][nt][1]),
                          "+f"(acc[mt][nt][2]), "+f"(acc[mt][nt][3])
                        : "r"(a[mt][0]), "r"(a[mt][1]), "r"(a[mt][2]), "r"(a[mt][3]),
                          "r"(b[nt][0]), "r"(b[nt][1]));
        }
    }

    #pragma unroll
    for (int nt = 0; nt < 8; nt++) {
        int col = n0 + wn + nt * 8 + lc * 2;
        float b0 = bias[col], b1 = bias[col + 1];
        #pragma unroll
        for (int mt = 0; mt < 4; mt++) {
            int r0 = m0 + wm + mt * 16 + lr;
            float2 o0, o1;
            if (round_out) {
                o0 = make_float2(f2tf32f(acc[mt][nt][0] + b0), f2tf32f(acc[mt][nt][1] + b1));
                o1 = make_float2(f2tf32f(acc[mt][nt][2] + b0), f2tf32f(acc[mt][nt][3] + b1));
            } else {
                o0 = make_float2(acc[mt][nt][0] + b0, acc[mt][nt][1] + b1);
                o1 = make_float2(acc[mt][nt][2] + b0, acc[mt][nt][3] + b1);
            }
            *(float2*)&C[(size_t)r0 * DD + col] = o0;
            *(float2*)&C[(size_t)(r0 + 8) * DD + col] = o1;
        }
    }
}

__global__ __launch_bounds__(128, 2) void gemm_qkv_fused(
    const float* __restrict__ A0, const float* __restrict__ A1, const float* __restrict__ A2,
    const float* __restrict__ W0, const float* __restrict__ W1, const float* __restrict__ W2,
    const float* __restrict__ b0, const float* __restrict__ b1, const float* __restrict__ b2,
    float* __restrict__ C0, float* __restrict__ C1, float* __restrict__ C2)
{
    int z = blockIdx.z;
    const float* A = (z == 0) ? A0 : (z == 1) ? A1 : A2;
    const float* W = (z == 0) ? W0 : (z == 1) ? W1 : W2;
    const float* bi = (z == 0) ? b0 : (z == 1) ? b1 : b2;
    float* C = (z == 0) ? C0 : (z == 1) ? C1 : C2;
    gemm_body(A, W, bi, C, 1);
}

__global__ __launch_bounds__(128, 2) void gemm_out_kernel(
    const float* __restrict__ A, const float* __restrict__ W,
    const float* __restrict__ bias, float* __restrict__ C)
{
    gemm_body(A, W, bias, C, 0);
}

// ---------------- Flash attention (causal), TF32 mma ----------------
// R13 structure: FQT=64, 128 threads, cp.async double-buffered K/V, heavy-first.
// log2e folded into Q scale; softmax uses raw ex2.approx.
#define FQT 64
#define FKT 64
#define FSTRK 68
#define FSTRV 72
#define FSTAGE (FKT * FSTRK + FKT * FSTRV)        // 8960 floats per stage
#define FLASH_SMEM (2 * FSTAGE * 4)               // 71680 bytes

__device__ __forceinline__ void flash_copy(
    const float* __restrict__ K, const float* __restrict__ V,
    size_t gbase, uint32_t sK, uint32_t sV, int tid)
{
    #pragma unroll
    for (int u = 0; u < 8; u++) {
        int idx = tid + u * 128;          // 0..1023
        int row = idx >> 4;               // 0..63
        int c   = idx & 15;               // 16B chunk
        cp_async16(sK + (uint32_t)(row * (FSTRK * 4) + c * 16),
                   K + gbase + (size_t)row * DD + c * 4);
        cp_async16(sV + (uint32_t)(row * (FSTRV * 4) + c * 16),
                   V + gbase + (size_t)row * DD + c * 4);
    }
}

__global__ __launch_bounds__(128, 3) void flash_mma_kernel(
    const float* __restrict__ Q, const float* __restrict__ K,
    const float* __restrict__ V, float* __restrict__ O)
{
    extern __shared__ float smem[];
    const uint32_t sbase = (uint32_t)__cvta_generic_to_shared(smem);

    const int tid  = threadIdx.x;
    const int lane = tid & 31;
    const int warp = tid >> 5;
    const int lr = lane >> 2;
    const int lc = lane & 3;
    const int qt = gridDim.x - 1 - blockIdx.x;   // heavy tiles first
    const int h  = blockIdx.y;
    const int b  = blockIdx.z;
    const int q0 = qt * FQT;
    const int lw = warp * 16 + lr;
    const float scale = 0.125f * 1.4426950408889634f;   // 1/sqrt(64) * log2(e)

    const int srcA = (lane & ~3) + (lc >> 1);
    const int srcB = srcA + 2;
    const bool hi  = (lc & 1);

    const size_t hbase = ((size_t)(b * SS)) * DD + h * DKH;

    // issue tile-0 copy immediately
    flash_copy(K, V, hbase, sbase, sbase + FKT * FSTRK * 4, tid);
    CP_COMMIT();

    // ---- Q fragments to registers (scaled by 0.125*log2e, RNA-rounded to tf32) ----
    uint32_t qa[8][4];
    {
        const float* qr0 = Q + hbase + (size_t)(q0 + warp*16 + lr) * DD;
        const float* qr1 = qr0 + 8 * DD;
        #pragma unroll
        for (int ks = 0; ks < 8; ks++) {
            const int kb = ks * 8;
            qa[ks][0] = f2tf32(qr0[kb + lc] * scale);
            qa[ks][1] = f2tf32(qr1[kb + lc] * scale);
            qa[ks][2] = f2tf32(qr0[kb + 4 + lc] * scale);
            qa[ks][3] = f2tf32(qr1[kb + 4 + lc] * scale);
        }
    }

    float m0v = -1e30f, m1v = -1e30f, l0 = 0.f, l1 = 0.f;
    float o_acc[8][4];
    #pragma unroll
    for (int nt = 0; nt < 8; nt++)
        #pragma unroll
        for (int t = 0; t < 4; t++) o_acc[nt][t] = 0.f;

    const int ntiles = qt + 1;   // causal

    for (int t = 0; t < ntiles; t++) {
        // issue next tile's copy into the other buffer
        if (t + 1 < ntiles) {
            uint32_t nb = sbase + ((t + 1) & 1) * (FSTAGE * 4);
            flash_copy(K, V, hbase + (size_t)(t + 1) * FKT * DD,
                       nb, nb + FKT * FSTRK * 4, tid);
        }
        CP_COMMIT();
        CP_WAIT1();          // current tile's copy complete
        __syncthreads();

        const float* Ks = smem + (t & 1) * FSTAGE;
        const float* Vs = Ks + FKT * FSTRK;

        // ---- S = Q @ K^T  (in log2 domain) ----
        float s[8][4];
        #pragma unroll
        for (int nt = 0; nt < 8; nt++)
            #pragma unroll
            for (int x = 0; x < 4; x++) s[nt][x] = 0.f;

        #pragma unroll
        for (int ks = 0; ks < 8; ks++) {
            const int kb = ks * 8;
            #pragma unroll
            for (int nt = 0; nt < 8; nt++) {
                uint32_t b0 = __float_as_uint(Ks[(nt*8 + lr) * FSTRK + kb + lc]);
                uint32_t b1 = __float_as_uint(Ks[(nt*8 + lr) * FSTRK + kb + 4 + lc]);
                asm volatile(
                    "mma.sync.aligned.m16n8k8.row.col.f32.tf32.tf32.f32 "
                    "{%0,%1,%2,%3}, {%4,%5,%6,%7}, {%8,%9}, {%0,%1,%2,%3};"
                    : "+f"(s[nt][0]), "+f"(s[nt][1]), "+f"(s[nt][2]), "+f"(s[nt][3])
                    : "r"(qa[ks][0]), "r"(qa[ks][1]), "r"(qa[ks][2]), "r"(qa[ks][3]),
                      "r"(b0), "r"(b1));
            }
        }

        // ---- causal mask on diagonal tile ----
        if (t == qt) {
            #pragma unroll
            for (int nt = 0; nt < 8; nt++) {
                int c0 = nt * 8 + lc * 2;
                if (c0     > lw)     s[nt][0] = -1e30f;
                if (c0 + 1 > lw)     s[nt][1] = -1e30f;
                if (c0     > lw + 8) s[nt][2] = -1e30f;
                if (c0 + 1 > lw + 8) s[nt][3] = -1e30f;
            }
        }

        // ---- online softmax (log2 domain: ex2 instead of exp) ----
        float tm0 = -1e30f, tm1 = -1e30f;
        #pragma unroll
        for (int nt = 0; nt < 8; nt++) {
            tm0 = fmaxf(tm0, fmaxf(s[nt][0], s[nt][1]));
            tm1 = fmaxf(tm1, fmaxf(s[nt][2], s[nt][3]));
        }
        tm0 = fmaxf(tm0, __shfl_xor_sync(0xffffffffu, tm0, 1));
        tm0 = fmaxf(tm0, __shfl_xor_sync(0xffffffffu, tm0, 2));
        tm1 = fmaxf(tm1, __shfl_xor_sync(0xffffffffu, tm1, 1));
        tm1 = fmaxf(tm1, __shfl_xor_sync(0xffffffffu, tm1, 2));

        const float mn0 = fmaxf(m0v, tm0);
        const float mn1 = fmaxf(m1v, tm1);
        const float cr0 = ex2f(m0v - mn0);
        const float cr1 = ex2f(m1v - mn1);
        l0 *= cr0; l1 *= cr1;
        #pragma unroll
        for (int nt = 0; nt < 8; nt++) {
            o_acc[nt][0] *= cr0; o_acc[nt][1] *= cr0;
            o_acc[nt][2] *= cr1; o_acc[nt][3] *= cr1;
        }
        m0v = mn0; m1v = mn1;

        // ---- P = 2^(S - m), rounded tf32, in registers ----
        #pragma unroll
        for (int nt = 0; nt < 8; nt++) {
            float p0 = ex2f(s[nt][0] - mn0);
            float p1 = ex2f(s[nt][1] - mn0);
            float p2 = ex2f(s[nt][2] - mn1);
            float p3 = ex2f(s[nt][3] - mn1);
            l0 += p0 + p1;
            l1 += p2 + p3;
            s[nt][0] = f2tf32f(p0); s[nt][1] = f2tf32f(p1);
            s[nt][2] = f2tf32f(p2); s[nt][3] = f2tf32f(p3);
        }

        // ---- O += P @ V ; a-frags via quad shuffles ----
        #pragma unroll
        for (int ks = 0; ks < 8; ks++) {
            const int kb = ks * 8;
            float t0 = __shfl_sync(0xffffffffu, s[ks][0], srcA);
            float t1 = __shfl_sync(0xffffffffu, s[ks][1], srcA);
            float t2 = __shfl_sync(0xffffffffu, s[ks][2], srcA);
            float t3 = __shfl_sync(0xffffffffu, s[ks][3], srcA);
            float v0 = __shfl_sync(0xffffffffu, s[ks][0], srcB);
            float v1 = __shfl_sync(0xffffffffu, s[ks][1], srcB);
            float v2 = __shfl_sync(0xffffffffu, s[ks][2], srcB);
            float v3 = __shfl_sync(0xffffffffu, s[ks][3], srcB);
            uint32_t a0 = __float_as_uint(hi ? t1 : t0);
            uint32_t a1 = __float_as_uint(hi ? t3 : t2);
            uint32_t a2 = __float_as_uint(hi ? v1 : v0);
            uint32_t a3 = __float_as_uint(hi ? v3 : v2);
            #pragma unroll
            for (int nt = 0; nt < 8; nt++) {
                uint32_t b0 = __float_as_uint(Vs[(kb + lc)     * FSTRV + nt*8 + lr]);
                uint32_t b1 = __float_as_uint(Vs[(kb + 4 + lc) * FSTRV + nt*8 + lr]);
                asm volatile(
                    "mma.sync.aligned.m16n8k8.row.col.f32.tf32.tf32.f32 "
                    "{%0,%1,%2,%3}, {%4,%5,%6,%7}, {%8,%9}, {%0,%1,%2,%3};"
                    : "+f"(o_acc[nt][0]), "+f"(o_acc[nt][1]),
                      "+f"(o_acc[nt][2]), "+f"(o_acc[nt][3])
                    : "r"(a0), "r"(a1), "r"(a2), "r"(a3), "r"(b0), "r"(b1));
            }
        }
        __syncthreads();   // all warps done with buf[t&1] before it is overwritten
    }

    // ---- finalize (tf32-rounded X for the output GEMM) ----
    l0 += __shfl_xor_sync(0xffffffffu, l0, 1);
    l0 += __shfl_xor_sync(0xffffffffu, l0, 2);
    l1 += __shfl_xor_sync(0xffffffffu, l1, 1);
    l1 += __shfl_xor_sync(0xffffffffu, l1, 2);
    const float inv0 = 1.0f / l0;
    const float inv1 = 1.0f / l1;

    const size_t obase = hbase + (size_t)q0 * DD;
    #pragma unroll
    for (int nt = 0; nt < 8; nt++) {
        int col = nt * 8 + lc * 2;
        *(float2*)(O + obase + (size_t)(warp*16 + lr) * DD + col) =
            make_float2(f2tf32f(o_acc[nt][0] * inv0), f2tf32f(o_acc[nt][1] * inv0));
        *(float2*)(O + obase + (size_t)(warp*16 + lr + 8) * DD + col) =
            make_float2(f2tf32f(o_acc[nt][2] * inv1), f2tf32f(o_acc[nt][3] * inv1));
    }
}

// ---------------- launch ----------------
extern "C" void kernel_launch(void* const* d_in, const int* in_sizes, int n_in,
                              void* d_out, int out_size)
{
    const float* q  = (const float*)d_in[0];
    const float* k  = (const float*)d_in[1];
    const float* v  = (const float*)d_in[2];
    // d_in[3] = mask (compile-time causal — unused)
    const float* wq = (const float*)d_in[4];
    const float* bq = (const float*)d_in[5];
    const float* wk = (const float*)d_in[6];
    const float* bk = (const float*)d_in[7];
    const float* wv = (const float*)d_in[8];
    const float* bv = (const float*)d_in[9];
    const float* wo = (const float*)d_in[10];
    const float* bo = (const float*)d_in[11];
    float* out = (float*)d_out;

    void *pQ, *pK, *pV, *pX, *pqc, *pkc, *pvc, *pwc;
    cudaGetSymbolAddress(&pQ, g_Q);
    cudaGetSymbolAddress(&pK, g_K);
    cudaGetSymbolAddress(&pV, g_V);
    cudaGetSymbolAddress(&pX, g_X);
    cudaGetSymbolAddress(&pqc, g_qc);
    cudaGetSymbolAddress(&pkc, g_kc);
    cudaGetSymbolAddress(&pvc, g_vc);
    cudaGetSymbolAddress(&pwc, g_wc);
    float* gQ = (float*)pQ;   float* gK = (float*)pK;
    float* gV = (float*)pV;   float* gX = (float*)pX;
    float* qc = (float*)pqc;  float* kc = (float*)pkc;
    float* vc = (float*)pvc;
    float* wqc = (float*)pwc;
    float* wkc = wqc + DD * DD;
    float* wvc = wqc + 2 * DD * DD;
    float* woc = wqc + 3 * DD * DD;

    cudaFuncSetAttribute(flash_mma_kernel,
                         cudaFuncAttributeMaxDynamicSharedMemorySize, FLASH_SMEM);
    cudaFuncSetAttribute(gemm_qkv_fused,
                         cudaFuncAttributeMaxDynamicSharedMemorySize, GEMM_SMEM);
    cudaFuncSetAttribute(gemm_out_kernel,
                         cudaFuncAttributeMaxDynamicSharedMemorySize, GEMM_SMEM);

    prep_all<<<PREP_TOTAL / 256, 256>>>(q, k, v, wq, wk, wv, wo,
                                        qc, kc, vc, wqc, wkc, wvc, woc);

    dim3 ggrid(DD / 128, MROWS / 128, 3);   // (8, 32, 3)
    gemm_qkv_fused<<<ggrid, 128, GEMM_SMEM>>>(qc, kc, vc, wqc, wkc, wvc,
                                              bq, bk, bv, gQ, gK, gV);

    dim3 fgrid(SS / FQT, NH, BB);           // (32, 16, 2)
    flash_mma_kernel<<<fgrid, 128, FLASH_SMEM>>>(gQ, gK, gV, gX);

    dim3 ogrid(DD / 128, MROWS / 128);
    gemm_out_kernel<<<ogrid, 128, GEMM_SMEM>>>(gX, woc, bo, out);
}

// round 16
// speedup vs baseline: 1.7107x; 1.0360x over previous
#include <cuda_runtime.h>
#include <cuda_bf16.h>
#include <math.h>
#include <stdint.h>

// Problem constants
#define BB 2
#define SS 2048
#define DD 1024
#define NH 16
#define DKH 64
#define MROWS (BB * SS)   // 4096

// ---------------- scratch (device globals; no allocation allowed) ----------------
__device__ float g_Q[MROWS * DD];
__device__ float g_K[MROWS * DD];
__device__ float g_V[MROWS * DD];
__device__ float g_X[MROWS * DD];
__device__ float g_wc[4][DD * DD];

__device__ __forceinline__ uint32_t f2tf32(float x) {
    uint32_t r;
    asm("cvt.rna.tf32.f32 %0, %1;" : "=r"(r) : "f"(x));
    return r;
}
__device__ __forceinline__ float f2tf32f(float x) {
    return __uint_as_float(f2tf32(x));
}
__device__ __forceinline__ float ex2f(float x) {
    float r;
    asm("ex2.approx.f32 %0, %1;" : "=f"(r) : "f"(x));
    return r;
}

__device__ __forceinline__ void cp_async16(uint32_t dst, const void* src) {
    asm volatile("cp.async.cg.shared.global [%0], [%1], 16;" :: "r"(dst), "l"(src));
}
#define CP_COMMIT()  asm volatile("cp.async.commit_group;" ::: "memory")
#define CP_WAIT1()   asm volatile("cp.async.wait_group 1;" ::: "memory")

// ---------------- tf32 conversion prep (weights only) ----------------
#define NW4 (DD * DD / 4)      // 2^18
#define PREP_TOTAL (4 * NW4)   // 2^20

__global__ __launch_bounds__(256) void prep_w(
    const float* __restrict__ wq, const float* __restrict__ wk,
    const float* __restrict__ wv, const float* __restrict__ wo,
    float* __restrict__ wqc, float* __restrict__ wkc,
    float* __restrict__ wvc, float* __restrict__ woc)
{
    long i = (long)blockIdx.x * 256 + threadIdx.x;
    int r = (int)(i >> 18);
    long off = i & (NW4 - 1);
    const float4* s = (const float4*)(r == 0 ? wq : (r == 1 ? wk : (r == 2 ? wv : wo)));
    float4* d = (float4*)(r == 0 ? wqc : (r == 1 ? wkc : (r == 2 ? wvc : woc)));
    float4 t = s[off];
    t.x = f2tf32f(t.x); t.y = f2tf32f(t.y);
    t.z = f2tf32f(t.z); t.w = f2tf32f(t.w);
    d[off] = t;
}

// ---------------- TF32 GEMM, cp.async 3-stage, 4 warps, 64x64 warp tiles ----------------
// cvt_a: RNA-round A fragments in-register (A arrives raw fp32 in smem).
#define GST 3
#define GSTAGE_FLOATS 8192
#define GEMM_SMEM (GST * GSTAGE_FLOATS * 4)   // 98304 B

__device__ __forceinline__ void gemm_stage_copy(
    const float* __restrict__ A, const float* __restrict__ W,
    int m0, int n0, int k0, uint32_t sA, uint32_t sB, int tid)
{
    #pragma unroll
    for (int u = 0; u < 8; u++) {
        int idx = tid + u * 128;
        int row = idx >> 3;
        int c   = idx & 7;
        int swz = c ^ (row & 7);
        cp_async16(sA + (uint32_t)(row * 128 + swz * 16),
                   A + (size_t)(m0 + row) * DD + k0 + c * 4);
        cp_async16(sB + (uint32_t)(row * 128 + swz * 16),
                   W + (size_t)(n0 + row) * DD + k0 + c * 4);
    }
}

__device__ __forceinline__ void gemm_body(
    const float* __restrict__ A, const float* __restrict__ W,
    const float* __restrict__ bias, float* __restrict__ C,
    int round_out, int cvt_a)
{
    extern __shared__ float sm[];
    const uint32_t sbase = (uint32_t)__cvta_generic_to_shared(sm);

    const int tid  = threadIdx.x;
    const int lane = tid & 31;
    const int warp = tid >> 5;
    const int wm = (warp & 1) * 64;
    const int wn = (warp >> 1) * 64;
    const int m0 = blockIdx.y * 128;
    const int n0 = blockIdx.x * 128;
    const int lr = lane >> 2;
    const int lc = lane & 3;

    float acc[4][8][4];
    #pragma unroll
    for (int i = 0; i < 4; i++)
        #pragma unroll
        for (int j = 0; j < 8; j++)
            #pragma unroll
            for (int t = 0; t < 4; t++) acc[i][j][t] = 0.f;

    const int NIT = DD / 32;

    gemm_stage_copy(A, W, m0, n0, 0, sbase, sbase + 4096 * 4, tid);
    CP_COMMIT();
    gemm_stage_copy(A, W, m0, n0, 32,
                    sbase + GSTAGE_FLOATS * 4, sbase + (GSTAGE_FLOATS + 4096) * 4, tid);
    CP_COMMIT();

    for (int it = 0; it < NIT; it++) {
        CP_WAIT1();
        __syncthreads();

        if (it + 2 < NIT) {
            int slot = (it + 2) % GST;
            gemm_stage_copy(A, W, m0, n0, (it + 2) * 32,
                            sbase + (uint32_t)(slot * GSTAGE_FLOATS) * 4,
                            sbase + (uint32_t)(slot * GSTAGE_FLOATS + 4096) * 4, tid);
        }
        CP_COMMIT();

        const float* As = sm + (it % GST) * GSTAGE_FLOATS;
        const float* Bs = As + 4096;

        #pragma unroll
        for (int ks = 0; ks < 4; ks++) {
            const int sw0 = (((2 * ks)     ^ lr) << 2) + lc;
            const int sw1 = (((2 * ks + 1) ^ lr) << 2) + lc;
            uint32_t a[4][4], b[8][2];
            #pragma unroll
            for (int mt = 0; mt < 4; mt++) {
                int r = wm + mt * 16 + lr;
                if (cvt_a) {
                    a[mt][0] = f2tf32(As[r * 32 + sw0]);
                    a[mt][1] = f2tf32(As[(r + 8) * 32 + sw0]);
                    a[mt][2] = f2tf32(As[r * 32 + sw1]);
                    a[mt][3] = f2tf32(As[(r + 8) * 32 + sw1]);
                } else {
                    a[mt][0] = __float_as_uint(As[r * 32 + sw0]);
                    a[mt][1] = __float_as_uint(As[(r + 8) * 32 + sw0]);
                    a[mt][2] = __float_as_uint(As[r * 32 + sw1]);
                    a[mt][3] = __float_as_uint(As[(r + 8) * 32 + sw1]);
                }
            }
            #pragma unroll
            for (int nt = 0; nt < 8; nt++) {
                int cn = wn + nt * 8 + lr;
                b[nt][0] = __float_as_uint(Bs[cn * 32 + sw0]);
                b[nt][1] = __float_as_uint(Bs[cn * 32 + sw1]);
            }
            #pragma unroll
            for (int mt = 0; mt < 4; mt++)
                #pragma unroll
                for (int nt = 0; nt < 8; nt++)
                    asm volatile(
                        "mma.sync.aligned.m16n8k8.row.col.f32.tf32.tf32.f32 "
                        "{%0,%1,%2,%3}, {%4,%5,%6,%7}, {%8,%9}, {%0,%1,%2,%3};"
                        : "+f"(acc[mt][nt][0]), "+f"(acc[mt][nt][1]),
                          "+f"(acc[mt][nt][2]), "+f"(acc[mt][nt][3])
                        : "r"(a[mt][0]), "r"(a[mt][1]), "r"(a[mt][2]), "r"(a[mt][3]),
                          "r"(b[nt][0]), "r"(b[nt][1]));
        }
    }

    #pragma unroll
    for (int nt = 0; nt < 8; nt++) {
        int col = n0 + wn + nt * 8 + lc * 2;
        float b0 = bias[col], b1 = bias[col + 1];
        #pragma unroll
        for (int mt = 0; mt < 4; mt++) {
            int r0 = m0 + wm + mt * 16 + lr;
            float2 o0, o1;
            if (round_out) {
                o0 = make_float2(f2tf32f(acc[mt][nt][0] + b0), f2tf32f(acc[mt][nt][1] + b1));
                o1 = make_float2(f2tf32f(acc[mt][nt][2] + b0), f2tf32f(acc[mt][nt][3] + b1));
            } else {
                o0 = make_float2(acc[mt][nt][0] + b0, acc[mt][nt][1] + b1);
                o1 = make_float2(acc[mt][nt][2] + b0, acc[mt][nt][3] + b1);
            }
            *(float2*)&C[(size_t)r0 * DD + col] = o0;
            *(float2*)&C[(size_t)(r0 + 8) * DD + col] = o1;
        }
    }
}

__global__ __launch_bounds__(128, 2) void gemm_qkv_fused(
    const float* __restrict__ A0, const float* __restrict__ A1, const float* __restrict__ A2,
    const float* __restrict__ W0, const float* __restrict__ W1, const float* __restrict__ W2,
    const float* __restrict__ b0, const float* __restrict__ b1, const float* __restrict__ b2,
    float* __restrict__ C0, float* __restrict__ C1, float* __restrict__ C2)
{
    int z = blockIdx.z;
    const float* A = (z == 0) ? A0 : (z == 1) ? A1 : A2;
    const float* W = (z == 0) ? W0 : (z == 1) ? W1 : W2;
    const float* bi = (z == 0) ? b0 : (z == 1) ? b1 : b2;
    float* C = (z == 0) ? C0 : (z == 1) ? C1 : C2;
    gemm_body(A, W, bi, C, 1, 1);   // raw fp32 A -> RNA in register
}

__global__ __launch_bounds__(128, 2) void gemm_out_kernel(
    const float* __restrict__ A, const float* __restrict__ W,
    const float* __restrict__ bias, float* __restrict__ C)
{
    gemm_body(A, W, bias, C, 0, 0); // X already RNA-rounded by flash
}

// ---------------- Flash attention (causal), TF32 mma ----------------
// FQT=64, 128 threads, cp.async double-buffered K/V, heavy-first,
// log2e folded into Q scale, ex2 softmax, diagonal-tile mma skip.
#define FQT 64
#define FKT 64
#define FSTRK 68
#define FSTRV 72
#define FSTAGE (FKT * FSTRK + FKT * FSTRV)        // 8960 floats per stage
#define FLASH_SMEM (2 * FSTAGE * 4)               // 71680 bytes

__device__ __forceinline__ void flash_copy(
    const float* __restrict__ K, const float* __restrict__ V,
    size_t gbase, uint32_t sK, uint32_t sV, int tid)
{
    #pragma unroll
    for (int u = 0; u < 8; u++) {
        int idx = tid + u * 128;          // 0..1023
        int row = idx >> 4;               // 0..63
        int c   = idx & 15;               // 16B chunk
        cp_async16(sK + (uint32_t)(row * (FSTRK * 4) + c * 16),
                   K + gbase + (size_t)row * DD + c * 4);
        cp_async16(sV + (uint32_t)(row * (FSTRV * 4) + c * 16),
                   V + gbase + (size_t)row * DD + c * 4);
    }
}

__global__ __launch_bounds__(128, 3) void flash_mma_kernel(
    const float* __restrict__ Q, const float* __restrict__ K,
    const float* __restrict__ V, float* __restrict__ O)
{
    extern __shared__ float smem[];
    const uint32_t sbase = (uint32_t)__cvta_generic_to_shared(smem);

    const int tid  = threadIdx.x;
    const int lane = tid & 31;
    const int warp = tid >> 5;
    const int lr = lane >> 2;
    const int lc = lane & 3;
    const int qt = gridDim.x - 1 - blockIdx.x;   // heavy tiles first
    const int h  = blockIdx.y;
    const int b  = blockIdx.z;
    const int q0 = qt * FQT;
    const int lw = warp * 16 + lr;
    const float scale = 0.125f * 1.4426950408889634f;   // 1/sqrt(64) * log2(e)

    const int srcA = (lane & ~3) + (lc >> 1);
    const int srcB = srcA + 2;
    const bool hi  = (lc & 1);
    const int ntw = 2 * warp + 2;   // diag tile: this warp needs nt/ks < ntw

    const size_t hbase = ((size_t)(b * SS)) * DD + h * DKH;

    // issue tile-0 copy immediately
    flash_copy(K, V, hbase, sbase, sbase + FKT * FSTRK * 4, tid);
    CP_COMMIT();

    // ---- Q fragments to registers (scaled, RNA-rounded to tf32) ----
    uint32_t qa[8][4];
    {
        const float* qr0 = Q + hbase + (size_t)(q0 + warp*16 + lr) * DD;
        const float* qr1 = qr0 + 8 * DD;
        #pragma unroll
        for (int ks = 0; ks < 8; ks++) {
            const int kb = ks * 8;
            qa[ks][0] = f2tf32(qr0[kb + lc] * scale);
            qa[ks][1] = f2tf32(qr1[kb + lc] * scale);
            qa[ks][2] = f2tf32(qr0[kb + 4 + lc] * scale);
            qa[ks][3] = f2tf32(qr1[kb + 4 + lc] * scale);
        }
    }

    float m0v = -1e30f, m1v = -1e30f, l0 = 0.f, l1 = 0.f;
    float o_acc[8][4];
    #pragma unroll
    for (int nt = 0; nt < 8; nt++)
        #pragma unroll
        for (int t = 0; t < 4; t++) o_acc[nt][t] = 0.f;

    const int ntiles = qt + 1;   // causal

    for (int t = 0; t < ntiles; t++) {
        if (t + 1 < ntiles) {
            uint32_t nb = sbase + ((t + 1) & 1) * (FSTAGE * 4);
            flash_copy(K, V, hbase + (size_t)(t + 1) * FKT * DD,
                       nb, nb + FKT * FSTRK * 4, tid);
        }
        CP_COMMIT();
        CP_WAIT1();
        __syncthreads();

        const float* Ks = smem + (t & 1) * FSTAGE;
        const float* Vs = Ks + FKT * FSTRK;

        float s[8][4];
        #pragma unroll
        for (int nt = 0; nt < 8; nt++)
            #pragma unroll
            for (int x = 0; x < 4; x++) s[nt][x] = 0.f;

        if (t < qt) {
            // ---- full tile: S = Q @ K^T ----
            #pragma unroll
            for (int ks = 0; ks < 8; ks++) {
                const int kb = ks * 8;
                #pragma unroll
                for (int nt = 0; nt < 8; nt++) {
                    uint32_t b0 = __float_as_uint(Ks[(nt*8 + lr) * FSTRK + kb + lc]);
                    uint32_t b1 = __float_as_uint(Ks[(nt*8 + lr) * FSTRK + kb + 4 + lc]);
                    asm volatile(
                        "mma.sync.aligned.m16n8k8.row.col.f32.tf32.tf32.f32 "
                        "{%0,%1,%2,%3}, {%4,%5,%6,%7}, {%8,%9}, {%0,%1,%2,%3};"
                        : "+f"(s[nt][0]), "+f"(s[nt][1]), "+f"(s[nt][2]), "+f"(s[nt][3])
                        : "r"(qa[ks][0]), "r"(qa[ks][1]), "r"(qa[ks][2]), "r"(qa[ks][3]),
                          "r"(b0), "r"(b1));
                }
            }
        } else {
            // ---- diagonal tile: only nt < ntw can be unmasked for this warp ----
            #pragma unroll
            for (int ks = 0; ks < 8; ks++) {
                const int kb = ks * 8;
                for (int nt = 0; nt < ntw; nt++) {
                    uint32_t b0 = __float_as_uint(Ks[(nt*8 + lr) * FSTRK + kb + lc]);
                    uint32_t b1 = __float_as_uint(Ks[(nt*8 + lr) * FSTRK + kb + 4 + lc]);
                    asm volatile(
                        "mma.sync.aligned.m16n8k8.row.col.f32.tf32.tf32.f32 "
                        "{%0,%1,%2,%3}, {%4,%5,%6,%7}, {%8,%9}, {%0,%1,%2,%3};"
                        : "+f"(s[nt][0]), "+f"(s[nt][1]), "+f"(s[nt][2]), "+f"(s[nt][3])
                        : "r"(qa[ks][0]), "r"(qa[ks][1]), "r"(qa[ks][2]), "r"(qa[ks][3]),
                          "r"(b0), "r"(b1));
                }
            }
            // causal mask (also fills skipped nt with -1e30: c0 > lw there always)
            #pragma unroll
            for (int nt = 0; nt < 8; nt++) {
                int c0 = nt * 8 + lc * 2;
                if (c0     > lw)     s[nt][0] = -1e30f;
                if (c0 + 1 > lw)     s[nt][1] = -1e30f;
                if (c0     > lw + 8) s[nt][2] = -1e30f;
                if (c0 + 1 > lw + 8) s[nt][3] = -1e30f;
            }
        }

        // ---- online softmax (log2 domain) ----
        float tm0 = -1e30f, tm1 = -1e30f;
        #pragma unroll
        for (int nt = 0; nt < 8; nt++) {
            tm0 = fmaxf(tm0, fmaxf(s[nt][0], s[nt][1]));
            tm1 = fmaxf(tm1, fmaxf(s[nt][2], s[nt][3]));
        }
        tm0 = fmaxf(tm0, __shfl_xor_sync(0xffffffffu, tm0, 1));
        tm0 = fmaxf(tm0, __shfl_xor_sync(0xffffffffu, tm0, 2));
        tm1 = fmaxf(tm1, __shfl_xor_sync(0xffffffffu, tm1, 1));
        tm1 = fmaxf(tm1, __shfl_xor_sync(0xffffffffu, tm1, 2));

        const float mn0 = fmaxf(m0v, tm0);
        const float mn1 = fmaxf(m1v, tm1);
        const float cr0 = ex2f(m0v - mn0);
        const float cr1 = ex2f(m1v - mn1);
        l0 *= cr0; l1 *= cr1;
        #pragma unroll
        for (int nt = 0; nt < 8; nt++) {
            o_acc[nt][0] *= cr0; o_acc[nt][1] *= cr0;
            o_acc[nt][2] *= cr1; o_acc[nt][3] *= cr1;
        }
        m0v = mn0; m1v = mn1;

        // ---- P = 2^(S - m), rounded tf32, in registers ----
        #pragma unroll
        for (int nt = 0; nt < 8; nt++) {
            float p0 = ex2f(s[nt][0] - mn0);
            float p1 = ex2f(s[nt][1] - mn0);
            float p2 = ex2f(s[nt][2] - mn1);
            float p3 = ex2f(s[nt][3] - mn1);
            l0 += p0 + p1;
            l1 += p2 + p3;
            s[nt][0] = f2tf32f(p0); s[nt][1] = f2tf32f(p1);
            s[nt][2] = f2tf32f(p2); s[nt][3] = f2tf32f(p3);
        }

        // ---- O += P @ V ----
        if (t < qt) {
            #pragma unroll
            for (int ks = 0; ks < 8; ks++) {
                const int kb = ks * 8;
                float t0 = __shfl_sync(0xffffffffu, s[ks][0], srcA);
                float t1 = __shfl_sync(0xffffffffu, s[ks][1], srcA);
                float t2 = __shfl_sync(0xffffffffu, s[ks][2], srcA);
                float t3 = __shfl_sync(0xffffffffu, s[ks][3], srcA);
                float v0 = __shfl_sync(0xffffffffu, s[ks][0], srcB);
                float v1 = __shfl_sync(0xffffffffu, s[ks][1], srcB);
                float v2 = __shfl_sync(0xffffffffu, s[ks][2], srcB);
                float v3 = __shfl_sync(0xffffffffu, s[ks][3], srcB);
                uint32_t a0 = __float_as_uint(hi ? t1 : t0);
                uint32_t a1 = __float_as_uint(hi ? t3 : t2);
                uint32_t a2 = __float_as_uint(hi ? v1 : v0);
                uint32_t a3 = __float_as_uint(hi ? v3 : v2);
                #pragma unroll
                for (int nt = 0; nt < 8; nt++) {
                    uint32_t b0 = __float_as_uint(Vs[(kb + lc)     * FSTRV + nt*8 + lr]);
                    uint32_t b1 = __float_as_uint(Vs[(kb + 4 + lc) * FSTRV + nt*8 + lr]);
                    asm volatile(
                        "mma.sync.aligned.m16n8k8.row.col.f32.tf32.tf32.f32 "
                        "{%0,%1,%2,%3}, {%4,%5,%6,%7}, {%8,%9}, {%0,%1,%2,%3};"
                        : "+f"(o_acc[nt][0]), "+f"(o_acc[nt][1]),
                          "+f"(o_acc[nt][2]), "+f"(o_acc[nt][3])
                        : "r"(a0), "r"(a1), "r"(a2), "r"(a3), "r"(b0), "r"(b1));
                }
            }
        } else {
            // diagonal: P columns kb >= 8*ntw are all zero for this warp -> skip
            for (int ks = 0; ks < ntw; ks++) {
                const int kb = ks * 8;
                float t0 = __shfl_sync(0xffffffffu, s[ks][0], srcA);
                float t1 = __shfl_sync(0xffffffffu, s[ks][1], srcA);
                float t2 = __shfl_sync(0xffffffffu, s[ks][2], srcA);
                float t3 = __shfl_sync(0xffffffffu, s[ks][3], srcA);
                float v0 = __shfl_sync(0xffffffffu, s[ks][0], srcB);
                float v1 = __shfl_sync(0xffffffffu, s[ks][1], srcB);
                float v2 = __shfl_sync(0xffffffffu, s[ks][2], srcB);
                float v3 = __shfl_sync(0xffffffffu, s[ks][3], srcB);
                uint32_t a0 = __float_as_uint(hi ? t1 : t0);
                uint32_t a1 = __float_as_uint(hi ? t3 : t2);
                uint32_t a2 = __float_as_uint(hi ? v1 : v0);
                uint32_t a3 = __float_as_uint(hi ? v3 : v2);
                #pragma unroll
                for (int nt = 0; nt < 8; nt++) {
                    uint32_t b0 = __float_as_uint(Vs[(kb + lc)     * FSTRV + nt*8 + lr]);
                    uint32_t b1 = __float_as_uint(Vs[(kb + 4 + lc) * FSTRV + nt*8 + lr]);
                    asm volatile(
                        "mma.sync.aligned.m16n8k8.row.col.f32.tf32.tf32.f32 "
                        "{%0,%1,%2,%3}, {%4,%5,%6,%7}, {%8,%9}, {%0,%1,%2,%3};"
                        : "+f"(o_acc[nt][0]), "+f"(o_acc[nt][1]),
                          "+f"(o_acc[nt][2]), "+f"(o_acc[nt][3])
                        : "r"(a0), "r"(a1), "r"(a2), "r"(a3), "r"(b0), "r"(b1));
                }
            }
        }
        __syncthreads();   // all warps done with buf[t&1] before it is overwritten
    }

    // ---- finalize (tf32-rounded X for the output GEMM) ----
    l0 += __shfl_xor_sync(0xffffffffu, l0, 1);
    l0 += __shfl_xor_sync(0xffffffffu, l0, 2);
    l1 += __shfl_xor_sync(0xffffffffu, l1, 1);
    l1 += __shfl_xor_sync(0xffffffffu, l1, 2);
    const float inv0 = 1.0f / l0;
    const float inv1 = 1.0f / l1;

    const size_t obase = hbase + (size_t)q0 * DD;
    #pragma unroll
    for (int nt = 0; nt < 8; nt++) {
        int col = nt * 8 + lc * 2;
        *(float2*)(O + obase + (size_t)(warp*16 + lr) * DD + col) =
            make_float2(f2tf32f(o_acc[nt][0] * inv0), f2tf32f(o_acc[nt][1] * inv0));
        *(float2*)(O + obase + (size_t)(warp*16 + lr + 8) * DD + col) =
            make_float2(f2tf32f(o_acc[nt][2] * inv1), f2tf32f(o_acc[nt][3] * inv1));
    }
}

// ---------------- launch ----------------
extern "C" void kernel_launch(void* const* d_in, const int* in_sizes, int n_in,
                              void* d_out, int out_size)
{
    const float* q  = (const float*)d_in[0];
    const float* k  = (const float*)d_in[1];
    const float* v  = (const float*)d_in[2];
    // d_in[3] = mask (compile-time causal — unused)
    const float* wq = (const float*)d_in[4];
    const float* bq = (const float*)d_in[5];
    const float* wk = (const float*)d_in[6];
    const float* bk = (const float*)d_in[7];
    const float* wv = (const float*)d_in[8];
    const float* bv = (const float*)d_in[9];
    const float* wo = (const float*)d_in[10];
    const float* bo = (const float*)d_in[11];
    float* out = (float*)d_out;

    void *pQ, *pK, *pV, *pX, *pwc;
    cudaGetSymbolAddress(&pQ, g_Q);
    cudaGetSymbolAddress(&pK, g_K);
    cudaGetSymbolAddress(&pV, g_V);
    cudaGetSymbolAddress(&pX, g_X);
    cudaGetSymbolAddress(&pwc, g_wc);
    float* gQ = (float*)pQ;   float* gK = (float*)pK;
    float* gV = (float*)pV;   float* gX = (float*)pX;
    float* wqc = (float*)pwc;
    float* wkc = wqc + DD * DD;
    float* wvc = wqc + 2 * DD * DD;
    float* woc = wqc + 3 * DD * DD;

    cudaFuncSetAttribute(flash_mma_kernel,
                         cudaFuncAttributeMaxDynamicSharedMemorySize, FLASH_SMEM);
    cudaFuncSetAttribute(gemm_qkv_fused,
                         cudaFuncAttributeMaxDynamicSharedMemorySize, GEMM_SMEM);
    cudaFuncSetAttribute(gemm_out_kernel,
                         cudaFuncAttributeMaxDynamicSharedMemorySize, GEMM_SMEM);

    prep_w<<<PREP_TOTAL / 256, 256>>>(wq, wk, wv, wo, wqc, wkc, wvc, woc);

    dim3 ggrid(DD / 128, MROWS / 128, 3);   // (8, 32, 3)
    gemm_qkv_fused<<<ggrid, 128, GEMM_SMEM>>>(q, k, v, wqc, wkc, wvc,
                                              bq, bk, bv, gQ, gK, gV);

    dim3 fgrid(SS / FQT, NH, BB);           // (32, 16, 2)
    flash_mma_kernel<<<fgrid, 128, FLASH_SMEM>>>(gQ, gK, gV, gX);

    dim3 ogrid(DD / 128, MROWS / 128);
    gemm_out_kernel<<<ogrid, 128, GEMM_SMEM>>>(gX, woc, bo, out);
}